// round 1
// baseline (speedup 1.0000x reference)
#include <cuda_runtime.h>
#include <math.h>

#define B_  256
#define T_  256
#define E_  64
#define N_  512
#define V_  128
#define G4  2048   // 4*N

// ---- scratch (static device memory; no allocations) ----
__device__ float g_xz[(size_t)T_ * B_ * G4];   // [T,B,4N] input projections (+bias)
__device__ float g_hs[(size_t)T_ * B_ * N_];   // [T,B,N] hidden states for final dense
__device__ float g_h[2][B_ * N_];              // ping-pong h
__device__ float g_c[B_ * N_];                 // cell state (exclusively owned per block slice)

// ---------------------------------------------------------------------------
// init: load h_0, c_0 (part of the graph so replays are deterministic)
// ---------------------------------------------------------------------------
__global__ void init_kernel(const float* __restrict__ h0, const float* __restrict__ c0) {
    int i = blockIdx.x * blockDim.x + threadIdx.x;
    if (i < B_ * N_) {
        g_h[0][i] = h0[i];
        g_c[i]    = c0[i];
    }
}

// ---------------------------------------------------------------------------
// Kernel A: xz[r][g] = bias[g] + sum_e emb[X[b][t]][e] * Wx[e][g]
//   rows r = t*B + b (t-major), M=65536, K=64, Ncols=2048
//   tile 128x128, 256 threads, 8x8 microtile
// ---------------------------------------------------------------------------
__global__ void input_gemm(const int*   __restrict__ X,
                           const float* __restrict__ emb,
                           const float* __restrict__ Wx,
                           const float* __restrict__ bias) {
    __shared__ int   xid[128];
    __shared__ float As[32][129];   // [k][row], padded
    __shared__ float Bs[32][128];   // [k][col]

    const int tid = threadIdx.x;
    const int tx  = tid & 15;
    const int ty  = tid >> 4;
    const int r0  = blockIdx.y * 128;
    const int g0  = blockIdx.x * 128;

    if (tid < 128) {
        int r = r0 + tid;
        int t = r >> 8;          // r = t*256 + b
        int b = r & 255;
        xid[tid] = X[b * T_ + t];
    }

    float acc[8][8];
#pragma unroll
    for (int i = 0; i < 8; i++)
#pragma unroll
        for (int j = 0; j < 8; j++) acc[i][j] = 0.f;

    for (int kc = 0; kc < E_; kc += 32) {
        __syncthreads();
#pragma unroll
        for (int x = tid; x < 32 * 128; x += 256) {
            int row = x >> 5, k = x & 31;
            As[k][row] = emb[xid[row] * E_ + kc + k];
        }
#pragma unroll
        for (int x = tid; x < 32 * 128; x += 256) {
            int kk = x >> 7, cc = x & 127;
            Bs[kk][cc] = Wx[(kc + kk) * G4 + g0 + cc];
        }
        __syncthreads();

#pragma unroll
        for (int k = 0; k < 32; k++) {
            float a[8], bb[8];
#pragma unroll
            for (int i = 0; i < 8; i++) a[i]  = As[k][ty + i * 16];
#pragma unroll
            for (int j = 0; j < 8; j++) bb[j] = Bs[k][tx + j * 16];
#pragma unroll
            for (int i = 0; i < 8; i++)
#pragma unroll
                for (int j = 0; j < 8; j++) acc[i][j] += a[i] * bb[j];
        }
    }

#pragma unroll
    for (int i = 0; i < 8; i++) {
        int r = r0 + ty + i * 16;
#pragma unroll
        for (int j = 0; j < 8; j++) {
            int g = g0 + tx + j * 16;
            g_xz[(size_t)r * G4 + g] = acc[i][j] + bias[g];
        }
    }
}

// ---------------------------------------------------------------------------
// Kernel B (per timestep, fused): z = xz[t] + h_in @ Wh; gates; update c,h
//   Block owns 32 rows x 32 n-values, computes all 4 gate columns for them.
//   grid (16, 8) = 128 blocks, 256 threads, per-thread 4 gates x 4 rows.
// ---------------------------------------------------------------------------
__global__ void lstm_step(const float* __restrict__ Wh, int t) {
    __shared__ float As[64][33];    // h chunk [k][row], padded
    __shared__ float Bs[64][128];   // Wh chunk [k][gate*32 + j]

    const float* __restrict__ h_in  = g_h[t & 1];
    float*       __restrict__ h_out = g_h[(t + 1) & 1];

    const int tid = threadIdx.x;
    const int tx  = tid & 31;       // local n
    const int ty  = tid >> 5;       // 0..7 (row group)
    const int n0  = blockIdx.x * 32;
    const int r0  = blockIdx.y * 32;

    float acc[4][4];                // [gate][row_i]
#pragma unroll
    for (int g = 0; g < 4; g++)
#pragma unroll
        for (int i = 0; i < 4; i++) acc[g][i] = 0.f;

    for (int kc = 0; kc < N_; kc += 64) {
        __syncthreads();
#pragma unroll
        for (int x = tid; x < 64 * 32; x += 256) {
            int row = x >> 6, k = x & 63;
            As[k][row] = h_in[(r0 + row) * N_ + kc + k];
        }
#pragma unroll
        for (int x = tid; x < 64 * 128; x += 256) {
            int kk = x >> 7, cc = x & 127;
            int gi = cc >> 5, j = cc & 31;
            Bs[kk][cc] = Wh[(kc + kk) * G4 + gi * N_ + n0 + j];
        }
        __syncthreads();

#pragma unroll
        for (int k = 0; k < 64; k++) {
            float a[4], bb[4];
#pragma unroll
            for (int i = 0; i < 4; i++) a[i]  = As[k][ty + i * 8];
#pragma unroll
            for (int g = 0; g < 4; g++) bb[g] = Bs[k][g * 32 + tx];
#pragma unroll
            for (int g = 0; g < 4; g++)
#pragma unroll
                for (int i = 0; i < 4; i++) acc[g][i] += a[i] * bb[g];
        }
    }

    const int n = n0 + tx;
#pragma unroll
    for (int i = 0; i < 4; i++) {
        int row = r0 + ty + i * 8;
        size_t base = (size_t)t * B_ * G4 + (size_t)row * G4;
        float zi = acc[0][i] + g_xz[base + 0 * N_ + n];
        float zf = acc[1][i] + g_xz[base + 1 * N_ + n];
        float zg = acc[2][i] + g_xz[base + 2 * N_ + n];
        float zo = acc[3][i] + g_xz[base + 3 * N_ + n];

        float ig = 1.f / (1.f + expf(-zi));
        float fg = 1.f / (1.f + expf(-zf));
        float gg = tanhf(zg);
        float og = 1.f / (1.f + expf(-zo));

        int idx = row * N_ + n;
        float c  = fg * g_c[idx] + ig * gg;
        g_c[idx] = c;
        float h  = og * tanhf(c);
        h_out[idx] = h;
        g_hs[(size_t)t * B_ * N_ + idx] = h;
    }
}

// ---------------------------------------------------------------------------
// Kernel D: logits[b][t][v] = bd[v] + sum_n hs[t][b][n] * Wd[n][v]
//   rows r = t*B + b, M=65536, K=512, Ncols=128; tile 128x128 (all of V)
// ---------------------------------------------------------------------------
__global__ void out_gemm(const float* __restrict__ Wd,
                         const float* __restrict__ bd,
                         float*       __restrict__ out) {
    __shared__ float As[32][129];
    __shared__ float Bs[32][128];

    const int tid = threadIdx.x;
    const int tx  = tid & 15;
    const int ty  = tid >> 4;
    const int r0  = blockIdx.x * 128;

    float acc[8][8];
#pragma unroll
    for (int i = 0; i < 8; i++)
#pragma unroll
        for (int j = 0; j < 8; j++) acc[i][j] = 0.f;

    for (int kc = 0; kc < N_; kc += 32) {
        __syncthreads();
#pragma unroll
        for (int x = tid; x < 32 * 128; x += 256) {
            int row = x >> 5, k = x & 31;
            As[k][row] = g_hs[(size_t)(r0 + row) * N_ + kc + k];
        }
#pragma unroll
        for (int x = tid; x < 32 * 128; x += 256) {
            int kk = x >> 7, cc = x & 127;
            Bs[kk][cc] = Wd[(kc + kk) * V_ + cc];
        }
        __syncthreads();

#pragma unroll
        for (int k = 0; k < 32; k++) {
            float a[8], bb[8];
#pragma unroll
            for (int i = 0; i < 8; i++) a[i]  = As[k][ty + i * 16];
#pragma unroll
            for (int j = 0; j < 8; j++) bb[j] = Bs[k][tx + j * 16];
#pragma unroll
            for (int i = 0; i < 8; i++)
#pragma unroll
                for (int j = 0; j < 8; j++) acc[i][j] += a[i] * bb[j];
        }
    }

#pragma unroll
    for (int i = 0; i < 8; i++) {
        int r = r0 + ty + i * 16;
        int t = r >> 8;
        int b = r & 255;
#pragma unroll
        for (int j = 0; j < 8; j++) {
            int v = tx + j * 16;
            out[(size_t)b * T_ * V_ + (size_t)t * V_ + v] = acc[i][j] + bd[v];
        }
    }
}

// ---------------------------------------------------------------------------
extern "C" void kernel_launch(void* const* d_in, const int* in_sizes, int n_in,
                              void* d_out, int out_size) {
    const int*   X    = (const int*)  d_in[0];
    const float* h0   = (const float*)d_in[1];
    const float* c0   = (const float*)d_in[2];
    const float* emb  = (const float*)d_in[3];
    const float* Wx   = (const float*)d_in[4];
    const float* Wh   = (const float*)d_in[5];
    const float* bias = (const float*)d_in[6];
    const float* Wd   = (const float*)d_in[7];
    const float* bd   = (const float*)d_in[8];
    float* out = (float*)d_out;

    init_kernel<<<(B_ * N_ + 255) / 256, 256>>>(h0, c0);
    input_gemm<<<dim3(G4 / 128, (T_ * B_) / 128), 256>>>(X, emb, Wx, bias);

    for (int t = 0; t < T_; t++) {
        lstm_step<<<dim3(N_ / 32, B_ / 32), 256>>>(Wh, t);
    }

    out_gemm<<<(T_ * B_) / 128, 256>>>(Wd, bd, out);
}

// round 2
// speedup vs baseline: 1.3527x; 1.3527x over previous
#include <cuda_runtime.h>
#include <math.h>

#define B_  256
#define T_  256
#define E_  64
#define N_  512
#define V_  128
#define G4  2048   // 4*N
#define NBLK 128

// ---- scratch (static device memory; no allocations) ----
__device__ float g_xz[(size_t)T_ * B_ * G4];   // [T,B,4N] input projections (+bias)
__device__ float g_hs[(size_t)T_ * B_ * N_];   // [T,B,N] hidden states for final dense
__device__ float g_h[2][B_ * N_];              // ping-pong h
__device__ unsigned g_flags[NBLK * 32];        // grid barrier flags, 128B-padded

// ---------------------------------------------------------------------------
// packed f32x2 helpers
// ---------------------------------------------------------------------------
__device__ __forceinline__ unsigned long long pack2(float lo, float hi) {
    unsigned long long r;
    asm("mov.b64 %0, {%1, %2};" : "=l"(r) : "r"(__float_as_uint(lo)), "r"(__float_as_uint(hi)));
    return r;
}
__device__ __forceinline__ void unpack2(unsigned long long v, float& lo, float& hi) {
    unsigned a, b;
    asm("mov.b64 {%0, %1}, %2;" : "=r"(a), "=r"(b) : "l"(v));
    lo = __uint_as_float(a); hi = __uint_as_float(b);
}
__device__ __forceinline__ void ffma2(unsigned long long& d, unsigned long long a, unsigned long long b) {
    asm("fma.rn.f32x2 %0, %1, %2, %0;" : "+l"(d) : "l"(a), "l"(b));
}
__device__ __forceinline__ float sigf(float x) { return 1.f / (1.f + __expf(-x)); }

// ---------------------------------------------------------------------------
// init: load h_0, reset barrier flags (part of the graph -> replay-safe)
// ---------------------------------------------------------------------------
__global__ void init_kernel(const float* __restrict__ h0) {
    int i = blockIdx.x * blockDim.x + threadIdx.x;
    if (i < B_ * N_) g_h[0][i] = h0[i];
    if (i < NBLK)    g_flags[i * 32] = 0u;
}

// ---------------------------------------------------------------------------
// Kernel A: xz[r][g] = bias[g] + sum_e emb[X[b][t]][e] * Wx[e][g]
// ---------------------------------------------------------------------------
__global__ void input_gemm(const int*   __restrict__ X,
                           const float* __restrict__ emb,
                           const float* __restrict__ Wx,
                           const float* __restrict__ bias) {
    __shared__ int   xid[128];
    __shared__ float As[32][129];
    __shared__ float Bs[32][128];

    const int tid = threadIdx.x;
    const int tx  = tid & 15;
    const int ty  = tid >> 4;
    const int r0  = blockIdx.y * 128;
    const int g0  = blockIdx.x * 128;

    if (tid < 128) {
        int r = r0 + tid;
        int t = r >> 8;
        int b = r & 255;
        xid[tid] = X[b * T_ + t];
    }

    float acc[8][8];
#pragma unroll
    for (int i = 0; i < 8; i++)
#pragma unroll
        for (int j = 0; j < 8; j++) acc[i][j] = 0.f;

    for (int kc = 0; kc < E_; kc += 32) {
        __syncthreads();
#pragma unroll
        for (int x = tid; x < 32 * 128; x += 256) {
            int row = x >> 5, k = x & 31;
            As[k][row] = emb[xid[row] * E_ + kc + k];
        }
#pragma unroll
        for (int x = tid; x < 32 * 128; x += 256) {
            int kk = x >> 7, cc = x & 127;
            Bs[kk][cc] = Wx[(kc + kk) * G4 + g0 + cc];
        }
        __syncthreads();

#pragma unroll
        for (int k = 0; k < 32; k++) {
            float a[8], bb[8];
#pragma unroll
            for (int i = 0; i < 8; i++) a[i]  = As[k][ty + i * 16];
#pragma unroll
            for (int j = 0; j < 8; j++) bb[j] = Bs[k][tx + j * 16];
#pragma unroll
            for (int i = 0; i < 8; i++)
#pragma unroll
                for (int j = 0; j < 8; j++) acc[i][j] += a[i] * bb[j];
        }
    }

#pragma unroll
    for (int i = 0; i < 8; i++) {
        int r = r0 + ty + i * 16;
#pragma unroll
        for (int j = 0; j < 8; j++) {
            int g = g0 + tx + j * 16;
            g_xz[(size_t)r * G4 + g] = acc[i][j] + bias[g];
        }
    }
}

// ---------------------------------------------------------------------------
// Persistent LSTM recurrence: one launch, 256 timesteps, grid barrier per step.
//   128 blocks (4 row-groups of 64 batch-rows x 32 n-groups of 16 n).
//   Each block owns cols {gate*512 + n0 + j : gate 0..3, j 0..15} = 64 cols.
//   Wh slice [512][64] resident in SMEM for all 256 steps.
//   h staged per step into duplicated-float2 SMEM tiles; c kept in registers.
//   Inner loop uses packed fma.rn.f32x2 (FFMA2) -> 128 MAC/cyc/SM.
// dynamic smem layout:
//   [0, 128KB)          Whs  : float [512][64]   (Whs[k][gate*16+j])
//   [128KB, 160KB)      AsD0 : float2 [64][64]   (dup h, [row][k])
//   [160KB, 192KB)      AsD1 : float2 [64][64]
//   zs (z exchange tile, float[64][64]) reuses AsD0 after the GEMM.
// ---------------------------------------------------------------------------
extern __shared__ char smem_raw[];

__global__ void __launch_bounds__(256, 1)
lstm_persistent(const float* __restrict__ Wh, const float* __restrict__ c0) {
    float*  Whs  = (float*)smem_raw;
    float2* AsD0 = (float2*)(smem_raw + 512 * 64 * 4);
    float2* AsD1 = AsD0 + 64 * 64;

    const int tid = threadIdx.x;
    const int bid = blockIdx.x;
    const int cg  = bid & 31;          // n-group
    const int rg  = bid >> 5;          // row-group
    const int n0  = cg * 16;
    const int r0  = rg * 64;
    const int tx  = tid & 15;
    const int ty  = tid >> 4;

    // ---- load Wh slice once: Whs[k][g*16+j] = Wh[k][g*512+n0+j] ----
    for (int idx = tid; idx < 512 * 16; idx += 256) {
        int k = idx >> 4, q = idx & 15;
        int g = q >> 2, jj = (q & 3) * 4;
        float4 w = *(const float4*)(Wh + (size_t)k * G4 + g * N_ + n0 + jj);
        *(float4*)(Whs + (size_t)k * 64 + g * 16 + jj) = w;
    }

    // ---- cell state in registers for the whole run ----
    const int prow = tid >> 2;             // 0..63
    const int pj0  = (tid & 3) * 4;        // 0,4,8,12
    float4 creg = *(const float4*)(c0 + (size_t)(r0 + prow) * N_ + n0 + pj0);

    __syncthreads();

    const int gate = tx >> 2;
    const int j0g  = (tx & 3) * 4;

    for (int t = 0; t < T_; t++) {
        const float* __restrict__ h_in  = g_h[t & 1];
        float*       __restrict__ h_out = g_h[(t + 1) & 1];

        // acc init from xz (z = xz + h@Wh): acc2[i][jj] covers rows ty*4+i,
        // cols 4tx+2jj, 4tx+2jj+1 (col c = gate*16 + j).
        unsigned long long acc2[4][2];
        {
            const size_t xbase = (size_t)t * B_ * G4 + (size_t)gate * N_ + n0 + j0g;
#pragma unroll
            for (int i = 0; i < 4; i++) {
                float4 xz4 = __ldcg((const float4*)(g_xz + xbase + (size_t)(r0 + ty * 4 + i) * G4));
                acc2[i][0] = pack2(xz4.x, xz4.y);
                acc2[i][1] = pack2(xz4.z, xz4.w);
            }
        }

        // ---- GEMM over K=512 in 8 chunks of 64, double-buffered h staging ----
        const int lrow = tid >> 4;   // for h staging: 16 threads per row slice... (lin mapping below)
        float4 pf[4];
#pragma unroll
        for (int q = 0; q < 4; q++) {
            int lin = tid + q * 256;
            int row = lin >> 4, kq = lin & 15;
            pf[q] = __ldcg((const float4*)(h_in + (size_t)(r0 + row) * N_ + kq * 4));
        }
        (void)lrow;

        for (int kc = 0; kc < 8; kc++) {
            float2* buf = (kc & 1) ? AsD1 : AsD0;
            // store duplicated pairs: buf[row][k] = (h,h)
#pragma unroll
            for (int q = 0; q < 4; q++) {
                int lin = tid + q * 256;
                int row = lin >> 4, kq = lin & 15;
                float2* dst = buf + (size_t)row * 64 + kq * 4;
                dst[0] = make_float2(pf[q].x, pf[q].x);
                dst[1] = make_float2(pf[q].y, pf[q].y);
                dst[2] = make_float2(pf[q].z, pf[q].z);
                dst[3] = make_float2(pf[q].w, pf[q].w);
            }
            if (kc < 7) {
#pragma unroll
                for (int q = 0; q < 4; q++) {
                    int lin = tid + q * 256;
                    int row = lin >> 4, kq = lin & 15;
                    pf[q] = __ldcg((const float4*)(h_in + (size_t)(r0 + row) * N_ + (kc + 1) * 64 + kq * 4));
                }
            }
            __syncthreads();

            const float* wbase = Whs + (size_t)kc * 64 * 64 + tx * 4;
            const unsigned long long* a0 = (const unsigned long long*)(buf + (size_t)(ty * 4 + 0) * 64);
            const unsigned long long* a1 = (const unsigned long long*)(buf + (size_t)(ty * 4 + 1) * 64);
            const unsigned long long* a2 = (const unsigned long long*)(buf + (size_t)(ty * 4 + 2) * 64);
            const unsigned long long* a3 = (const unsigned long long*)(buf + (size_t)(ty * 4 + 3) * 64);

#pragma unroll 16
            for (int k = 0; k < 64; k++) {
                ulonglong2 bv = *(const ulonglong2*)(wbase + (size_t)k * 64);
                unsigned long long v0 = a0[k], v1 = a1[k], v2 = a2[k], v3 = a3[k];
                ffma2(acc2[0][0], v0, bv.x); ffma2(acc2[0][1], v0, bv.y);
                ffma2(acc2[1][0], v1, bv.x); ffma2(acc2[1][1], v1, bv.y);
                ffma2(acc2[2][0], v2, bv.x); ffma2(acc2[2][1], v2, bv.y);
                ffma2(acc2[3][0], v3, bv.x); ffma2(acc2[3][1], v3, bv.y);
            }
            __syncthreads();
        }

        // ---- exchange z through SMEM (gate fusion needs all 4 gates per n) ----
        float* zs = (float*)AsD0;   // [64][64], col c = gate*16 + j
#pragma unroll
        for (int i = 0; i < 4; i++) {
            float x0, x1, x2, x3;
            unpack2(acc2[i][0], x0, x1);
            unpack2(acc2[i][1], x2, x3);
            float4 v = make_float4(x0, x1, x2, x3);
            *(float4*)(zs + (size_t)(ty * 4 + i) * 64 + tx * 4) = v;
        }
        __syncthreads();

        // ---- pointwise gates + c/h update (c in registers) ----
        {
            const float* zr = zs + (size_t)prow * 64 + pj0;
            float4 zi = *(const float4*)(zr + 0);
            float4 zf = *(const float4*)(zr + 16);
            float4 zg = *(const float4*)(zr + 32);
            float4 zo = *(const float4*)(zr + 48);

            float4 hv;
            creg.x = sigf(zf.x) * creg.x + sigf(zi.x) * tanhf(zg.x); hv.x = sigf(zo.x) * tanhf(creg.x);
            creg.y = sigf(zf.y) * creg.y + sigf(zi.y) * tanhf(zg.y); hv.y = sigf(zo.y) * tanhf(creg.y);
            creg.z = sigf(zf.z) * creg.z + sigf(zi.z) * tanhf(zg.z); hv.z = sigf(zo.z) * tanhf(creg.z);
            creg.w = sigf(zf.w) * creg.w + sigf(zi.w) * tanhf(zg.w); hv.w = sigf(zo.w) * tanhf(creg.w);

            size_t off = (size_t)(r0 + prow) * N_ + n0 + pj0;
            *(float4*)(h_out + off) = hv;
            *(float4*)(g_hs + (size_t)t * B_ * N_ + off) = hv;
        }

        // ---- grid barrier (release/acquire flags; all 128 blocks resident) ----
        __threadfence();
        __syncthreads();
        if (tid == 0) {
            asm volatile("st.global.release.gpu.u32 [%0], %1;"
                         :: "l"(&g_flags[bid * 32]), "r"((unsigned)(t + 1)) : "memory");
        }
        if (tid < NBLK) {
            unsigned v;
            do {
                asm volatile("ld.global.acquire.gpu.u32 %0, [%1];"
                             : "=r"(v) : "l"(&g_flags[tid * 32]) : "memory");
                if (v >= (unsigned)(t + 1)) break;
                __nanosleep(20);
            } while (true);
        }
        __syncthreads();
    }
}

// ---------------------------------------------------------------------------
// Kernel D: logits[b][t][v] = bd[v] + sum_n hs[t][b][n] * Wd[n][v]
// ---------------------------------------------------------------------------
__global__ void out_gemm(const float* __restrict__ Wd,
                         const float* __restrict__ bd,
                         float*       __restrict__ out) {
    __shared__ float As[32][129];
    __shared__ float Bs[32][128];

    const int tid = threadIdx.x;
    const int tx  = tid & 15;
    const int ty  = tid >> 4;
    const int r0  = blockIdx.x * 128;

    float acc[8][8];
#pragma unroll
    for (int i = 0; i < 8; i++)
#pragma unroll
        for (int j = 0; j < 8; j++) acc[i][j] = 0.f;

    for (int kc = 0; kc < N_; kc += 32) {
        __syncthreads();
#pragma unroll
        for (int x = tid; x < 32 * 128; x += 256) {
            int row = x >> 5, k = x & 31;
            As[k][row] = g_hs[(size_t)(r0 + row) * N_ + kc + k];
        }
#pragma unroll
        for (int x = tid; x < 32 * 128; x += 256) {
            int kk = x >> 7, cc = x & 127;
            Bs[kk][cc] = Wd[(kc + kk) * V_ + cc];
        }
        __syncthreads();

#pragma unroll
        for (int k = 0; k < 32; k++) {
            float a[8], bb[8];
#pragma unroll
            for (int i = 0; i < 8; i++) a[i]  = As[k][ty + i * 16];
#pragma unroll
            for (int j = 0; j < 8; j++) bb[j] = Bs[k][tx + j * 16];
#pragma unroll
            for (int i = 0; i < 8; i++)
#pragma unroll
                for (int j = 0; j < 8; j++) acc[i][j] += a[i] * bb[j];
        }
    }

#pragma unroll
    for (int i = 0; i < 8; i++) {
        int r = r0 + ty + i * 16;
        int t = r >> 8;
        int b = r & 255;
#pragma unroll
        for (int j = 0; j < 8; j++) {
            int v = tx + j * 16;
            out[(size_t)b * T_ * V_ + (size_t)t * V_ + v] = acc[i][j] + bd[v];
        }
    }
}

// ---------------------------------------------------------------------------
extern "C" void kernel_launch(void* const* d_in, const int* in_sizes, int n_in,
                              void* d_out, int out_size) {
    const int*   X    = (const int*)  d_in[0];
    const float* h0   = (const float*)d_in[1];
    const float* c0   = (const float*)d_in[2];
    const float* emb  = (const float*)d_in[3];
    const float* Wx   = (const float*)d_in[4];
    const float* Wh   = (const float*)d_in[5];
    const float* bias = (const float*)d_in[6];
    const float* Wd   = (const float*)d_in[7];
    const float* bd   = (const float*)d_in[8];
    float* out = (float*)d_out;

    const int smem_bytes = 512 * 64 * 4 + 2 * 64 * 64 * 8;  // 192KB
    cudaFuncSetAttribute(lstm_persistent, cudaFuncAttributeMaxDynamicSharedMemorySize, smem_bytes);

    init_kernel<<<(B_ * N_ + 255) / 256, 256>>>(h0);
    input_gemm<<<dim3(G4 / 128, (T_ * B_) / 128), 256>>>(X, emb, Wx, bias);
    lstm_persistent<<<NBLK, 256, smem_bytes>>>(Wh, c0);
    out_gemm<<<(T_ * B_) / 128, 256>>>(Wd, bd, out);
}

// round 5
// speedup vs baseline: 2.5229x; 1.8650x over previous
#include <cuda_runtime.h>
#include <cuda_bf16.h>
#include <math.h>

#define B_  256
#define T_  256
#define E_  64
#define N_  512
#define V_  128
#define G4  2048   // 4*N
#define NBLK 128

#define KS_BF 520   // Whs row stride in bf16 (col-major-by-col: [col][k]), padded
#define KS_W  260   // same in 32-bit words
#define HA_BF 72    // hA row stride in bf16 ([row][k] per 64-k chunk), padded
#define HA_W  36    // same in 32-bit words
#define Z_STRIDE 68 // z-exchange float stride

// SMEM byte offsets
#define OFF_WHI 0
#define OFF_WLO (64 * KS_BF * 2)                 // 66560
#define OFF_HA  (2 * 64 * KS_BF * 2)             // 133120
#define HA_BYTES (64 * HA_BF * 2)                // 9216
#define SMEM_TOTAL_LSTM (OFF_HA + 4 * HA_BYTES)  // 169984

// ---- scratch (static device memory; no allocations) ----
__device__ float g_xz[(size_t)T_ * B_ * G4];   // [T,B,4N] input projections (+bias)
__device__ float g_hs[(size_t)T_ * B_ * N_];   // [T,B,N] hidden states for final dense
__device__ float g_h[2][B_ * N_];              // ping-pong h
__device__ unsigned g_flags[NBLK * 32];        // grid barrier flags, 128B-padded

// ---------------------------------------------------------------------------
__device__ __forceinline__ float sigf(float x) { return 1.f / (1.f + __expf(-x)); }

__device__ __forceinline__ void mma_bf16(float* d, const unsigned* a, const unsigned* b) {
    asm volatile(
        "mma.sync.aligned.m16n8k16.row.col.f32.bf16.bf16.f32 "
        "{%0,%1,%2,%3}, {%4,%5,%6,%7}, {%8,%9}, {%0,%1,%2,%3};"
        : "+f"(d[0]), "+f"(d[1]), "+f"(d[2]), "+f"(d[3])
        : "r"(a[0]), "r"(a[1]), "r"(a[2]), "r"(a[3]), "r"(b[0]), "r"(b[1]));
}

// split float x into bf16 hi + bf16 lo (x ~= hi + lo, ~16 effective mantissa bits)
__device__ __forceinline__ void bf16_split(float x, __nv_bfloat16& hi, __nv_bfloat16& lo) {
    hi = __float2bfloat16(x);
    lo = __float2bfloat16(x - __bfloat162float(hi));
}

// pack two bf16 into a 32-bit word: lo in bits[0:16), hi in bits[16:32)
__device__ __forceinline__ unsigned pack_bf2(__nv_bfloat16 lo, __nv_bfloat16 hi) {
    unsigned short ul = __bfloat16_as_ushort(lo);
    unsigned short uh = __bfloat16_as_ushort(hi);
    return (unsigned)ul | ((unsigned)uh << 16);
}

// ---------------------------------------------------------------------------
// init: load h_0, reset barrier flags (part of the graph -> replay-safe)
// ---------------------------------------------------------------------------
__global__ void init_kernel(const float* __restrict__ h0) {
    int i = blockIdx.x * blockDim.x + threadIdx.x;
    if (i < B_ * N_) g_h[0][i] = h0[i];
    if (i < NBLK)    g_flags[i * 32] = 0u;
}

// ---------------------------------------------------------------------------
// Kernel A: xz[r][g] = bias[g] + sum_e emb[X[b][t]][e] * Wx[e][g]
// ---------------------------------------------------------------------------
__global__ void input_gemm(const int*   __restrict__ X,
                           const float* __restrict__ emb,
                           const float* __restrict__ Wx,
                           const float* __restrict__ bias) {
    __shared__ int   xid[128];
    __shared__ float As[32][129];
    __shared__ float Bs[32][128];

    const int tid = threadIdx.x;
    const int tx  = tid & 15;
    const int ty  = tid >> 4;
    const int r0  = blockIdx.y * 128;
    const int g0  = blockIdx.x * 128;

    if (tid < 128) {
        int r = r0 + tid;
        int t = r >> 8;
        int b = r & 255;
        xid[tid] = X[b * T_ + t];
    }

    float acc[8][8];
#pragma unroll
    for (int i = 0; i < 8; i++)
#pragma unroll
        for (int j = 0; j < 8; j++) acc[i][j] = 0.f;

    for (int kc = 0; kc < E_; kc += 32) {
        __syncthreads();
#pragma unroll
        for (int x = tid; x < 32 * 128; x += 256) {
            int row = x >> 5, k = x & 31;
            As[k][row] = emb[xid[row] * E_ + kc + k];
        }
#pragma unroll
        for (int x = tid; x < 32 * 128; x += 256) {
            int kk = x >> 7, cc = x & 127;
            Bs[kk][cc] = Wx[(kc + kk) * G4 + g0 + cc];
        }
        __syncthreads();

#pragma unroll
        for (int k = 0; k < 32; k++) {
            float a[8], bb[8];
#pragma unroll
            for (int i = 0; i < 8; i++) a[i]  = As[k][ty + i * 16];
#pragma unroll
            for (int j = 0; j < 8; j++) bb[j] = Bs[k][tx + j * 16];
#pragma unroll
            for (int i = 0; i < 8; i++)
#pragma unroll
                for (int j = 0; j < 8; j++) acc[i][j] += a[i] * bb[j];
        }
    }

#pragma unroll
    for (int i = 0; i < 8; i++) {
        int r = r0 + ty + i * 16;
#pragma unroll
        for (int j = 0; j < 8; j++) {
            int g = g0 + tx + j * 16;
            g_xz[(size_t)r * G4 + g] = acc[i][j] + bias[g];
        }
    }
}

// ---------------------------------------------------------------------------
// Persistent LSTM recurrence, bf16x2 error-compensated tensor-core GEMM.
//   128 blocks: (4 row-groups x 64 rows) x (32 n-groups x 16 n).
//   Block cols c = gate*16 + j <-> Wh col gate*512 + n0 + j (64 cols).
//   Whs_hi/Whs_lo [col][k] bf16 (stride 520), resident all 256 steps.
//   h split hi/lo per 64-k chunk (double-buffered). 8 warps, warp tile
//   16 rows x 32 cols, mma.m16n8k16: per k16, per n8-subtile 3 MMAs
//   (hi*hi + hi*lo + lo*hi), fp32 accumulate. c in registers; gate fusion
//   via SMEM z-exchange. dynamic smem = 169984 B.
// ---------------------------------------------------------------------------
extern __shared__ char smem_raw[];

__global__ void __launch_bounds__(256, 1)
lstm_persistent(const float* __restrict__ Wh, const float* __restrict__ c0) {
    __nv_bfloat16* WhHi = (__nv_bfloat16*)(smem_raw + OFF_WHI);
    __nv_bfloat16* WhLo = (__nv_bfloat16*)(smem_raw + OFF_WLO);
    const unsigned* WhHiW = (const unsigned*)WhHi;
    const unsigned* WhLoW = (const unsigned*)WhLo;

    char* hBase = smem_raw + OFF_HA;   // 4 buffers: hi0, lo0, hi1, lo1

    const int tid  = threadIdx.x;
    const int bid  = blockIdx.x;
    const int cg   = bid & 31;          // n-group
    const int rg   = bid >> 5;          // row-group
    const int n0   = cg * 16;
    const int r0   = rg * 64;
    const int lane = tid & 31;
    const int wid  = tid >> 5;
    const int wr   = (wid & 3) * 16;    // warp row offset in tile
    const int wc   = (wid >> 2) * 32;   // warp col offset in tile
    const int g4r  = lane >> 2;         // 0..7
    const int lk   = lane & 3;          // 0..3
    const int lx2  = lk * 2;

    // ---- load + split Wh slice once: WhHi/WhLo[col][k], col = g*16+j ----
    for (int idx = tid; idx < 512 * 16; idx += 256) {
        int k = idx >> 4, q = idx & 15;
        int g = q >> 2, jj = (q & 3) * 4;
        float4 w = *(const float4*)(Wh + (size_t)k * G4 + g * N_ + n0 + jj);
        int cb = g * 16 + jj;
        __nv_bfloat16 hi, lo;
        bf16_split(w.x, hi, lo); WhHi[(cb + 0) * KS_BF + k] = hi; WhLo[(cb + 0) * KS_BF + k] = lo;
        bf16_split(w.y, hi, lo); WhHi[(cb + 1) * KS_BF + k] = hi; WhLo[(cb + 1) * KS_BF + k] = lo;
        bf16_split(w.z, hi, lo); WhHi[(cb + 2) * KS_BF + k] = hi; WhLo[(cb + 2) * KS_BF + k] = lo;
        bf16_split(w.w, hi, lo); WhHi[(cb + 3) * KS_BF + k] = hi; WhLo[(cb + 3) * KS_BF + k] = lo;
    }

    // ---- cell state in registers for the whole run ----
    const int prow = tid >> 2;             // 0..63
    const int pj0  = (tid & 3) * 4;        // 0,4,8,12
    float4 creg = *(const float4*)(c0 + (size_t)(r0 + prow) * N_ + n0 + pj0);

    __syncthreads();

    // staging address components (per thread: 4 float4 = 16 floats of h chunk)
    const int srow0 = tid >> 4;            // rows tid>>4, +16, +32, +48
    const int skq   = tid & 15;            // k quad: floats [skq*4, skq*4+4)

    for (int t = 0; t < T_; t++) {
        const float* __restrict__ h_in  = g_h[t & 1];
        float*       __restrict__ h_out = g_h[(t + 1) & 1];

        // ---- acc init from xz (z = xz + h@Wh), mma D-fragment layout ----
        float acc[4][4];
        {
            const int rlo = r0 + wr + g4r;
#pragma unroll
            for (int sub = 0; sub < 4; sub++) {
                int c    = wc + sub * 8 + lx2;
                int gate = c >> 4, jj = c & 15;
                size_t base = (size_t)t * B_ * G4 + (size_t)gate * N_ + n0 + jj;
                float2 xlo = __ldcg((const float2*)(g_xz + base + (size_t)rlo * G4));
                float2 xhi = __ldcg((const float2*)(g_xz + base + (size_t)(rlo + 8) * G4));
                acc[sub][0] = xlo.x; acc[sub][1] = xlo.y;
                acc[sub][2] = xhi.x; acc[sub][3] = xhi.y;
            }
        }

        // ---- GEMM over K=512 in 8 chunks of 64, double-buffered h split ----
        float4 pf[4];
#pragma unroll
        for (int q = 0; q < 4; q++) {
            pf[q] = __ldcg((const float4*)(h_in + (size_t)(r0 + srow0 + q * 16) * N_ + skq * 4));
        }

        for (int kc = 0; kc < 8; kc++) {
            unsigned* hHiW = (unsigned*)(hBase + (kc & 1) * 2 * HA_BYTES);
            unsigned* hLoW = hHiW + HA_BYTES / 4;

            // split + store chunk: hA[row][k] bf16, stride HA_BF
#pragma unroll
            for (int q = 0; q < 4; q++) {
                int row = srow0 + q * 16;
                float4 v = pf[q];
                __nv_bfloat16 h0b, l0b, h1b, l1b, h2b, l2b, h3b, l3b;
                bf16_split(v.x, h0b, l0b); bf16_split(v.y, h1b, l1b);
                bf16_split(v.z, h2b, l2b); bf16_split(v.w, h3b, l3b);
                unsigned hw0 = pack_bf2(h0b, h1b);
                unsigned hw1 = pack_bf2(h2b, h3b);
                unsigned lw0 = pack_bf2(l0b, l1b);
                unsigned lw1 = pack_bf2(l2b, l3b);
                int widx = row * HA_W + skq * 2;
                *(uint2*)(hHiW + widx) = make_uint2(hw0, hw1);
                *(uint2*)(hLoW + widx) = make_uint2(lw0, lw1);
            }
            if (kc < 7) {
#pragma unroll
                for (int q = 0; q < 4; q++) {
                    pf[q] = __ldcg((const float4*)(h_in + (size_t)(r0 + srow0 + q * 16) * N_ + (kc + 1) * 64 + skq * 4));
                }
            }
            __syncthreads();

            const int aBase = (wr + g4r) * HA_W + lk;
            const int kAbs  = kc * 32 + lk;   // word offset into Whs k-dim
#pragma unroll
            for (int k16 = 0; k16 < 4; k16++) {
                const int aw = aBase + k16 * 8;
                unsigned aHi[4], aLo[4];
                aHi[0] = hHiW[aw];              aHi[1] = hHiW[aw + 8 * HA_W];
                aHi[2] = hHiW[aw + 4];          aHi[3] = hHiW[aw + 8 * HA_W + 4];
                aLo[0] = hLoW[aw];              aLo[1] = hLoW[aw + 8 * HA_W];
                aLo[2] = hLoW[aw + 4];          aLo[3] = hLoW[aw + 8 * HA_W + 4];
#pragma unroll
                for (int sub = 0; sub < 4; sub++) {
                    const int col = wc + sub * 8 + g4r;
                    const int bw  = col * KS_W + kAbs + k16 * 8;
                    unsigned bHi[2], bLo[2];
                    bHi[0] = WhHiW[bw]; bHi[1] = WhHiW[bw + 4];
                    bLo[0] = WhLoW[bw]; bLo[1] = WhLoW[bw + 4];
                    mma_bf16(acc[sub], aHi, bHi);
                    mma_bf16(acc[sub], aHi, bLo);
                    mma_bf16(acc[sub], aLo, bHi);
                }
            }
            __syncthreads();
        }

        // ---- exchange z through SMEM (gate fusion needs all 4 gates per n) ----
        float* zs = (float*)hBase;   // [64][Z_STRIDE], col c = gate*16 + j
        {
            const int rl = wr + g4r;
#pragma unroll
            for (int sub = 0; sub < 4; sub++) {
                int c = wc + sub * 8 + lx2;
                *(float2*)(zs + (size_t)rl * Z_STRIDE + c)       = make_float2(acc[sub][0], acc[sub][1]);
                *(float2*)(zs + (size_t)(rl + 8) * Z_STRIDE + c) = make_float2(acc[sub][2], acc[sub][3]);
            }
        }
        __syncthreads();

        // ---- pointwise gates + c/h update (c in registers) ----
        {
            const float* zr = zs + (size_t)prow * Z_STRIDE + pj0;
            float4 zi = *(const float4*)(zr + 0);
            float4 zf = *(const float4*)(zr + 16);
            float4 zg = *(const float4*)(zr + 32);
            float4 zo = *(const float4*)(zr + 48);

            float4 hv;
            creg.x = sigf(zf.x) * creg.x + sigf(zi.x) * tanhf(zg.x); hv.x = sigf(zo.x) * tanhf(creg.x);
            creg.y = sigf(zf.y) * creg.y + sigf(zi.y) * tanhf(zg.y); hv.y = sigf(zo.y) * tanhf(creg.y);
            creg.z = sigf(zf.z) * creg.z + sigf(zi.z) * tanhf(zg.z); hv.z = sigf(zo.z) * tanhf(creg.z);
            creg.w = sigf(zf.w) * creg.w + sigf(zi.w) * tanhf(zg.w); hv.w = sigf(zo.w) * tanhf(creg.w);

            size_t off = (size_t)(r0 + prow) * N_ + n0 + pj0;
            *(float4*)(h_out + off) = hv;
            *(float4*)(g_hs + (size_t)t * B_ * N_ + off) = hv;
        }

        // ---- grid barrier (release/acquire flags; all 128 blocks resident) ----
        __threadfence();
        __syncthreads();
        if (tid == 0) {
            asm volatile("st.global.release.gpu.u32 [%0], %1;"
                         :: "l"(&g_flags[bid * 32]), "r"((unsigned)(t + 1)) : "memory");
        }
        if (tid < NBLK) {
            unsigned v;
            do {
                asm volatile("ld.global.acquire.gpu.u32 %0, [%1];"
                             : "=r"(v) : "l"(&g_flags[tid * 32]) : "memory");
                if (v >= (unsigned)(t + 1)) break;
                __nanosleep(20);
            } while (true);
        }
        __syncthreads();
    }
}

// ---------------------------------------------------------------------------
// Kernel D: logits[b][t][v] = bd[v] + sum_n hs[t][b][n] * Wd[n][v]
// ---------------------------------------------------------------------------
__global__ void out_gemm(const float* __restrict__ Wd,
                         const float* __restrict__ bd,
                         float*       __restrict__ out) {
    __shared__ float As[32][129];
    __shared__ float Bs[32][128];

    const int tid = threadIdx.x;
    const int tx  = tid & 15;
    const int ty  = tid >> 4;
    const int r0  = blockIdx.x * 128;

    float acc[8][8];
#pragma unroll
    for (int i = 0; i < 8; i++)
#pragma unroll
        for (int j = 0; j < 8; j++) acc[i][j] = 0.f;

    for (int kc = 0; kc < N_; kc += 32) {
        __syncthreads();
#pragma unroll
        for (int x = tid; x < 32 * 128; x += 256) {
            int row = x >> 5, k = x & 31;
            As[k][row] = g_hs[(size_t)(r0 + row) * N_ + kc + k];
        }
#pragma unroll
        for (int x = tid; x < 32 * 128; x += 256) {
            int kk = x >> 7, cc = x & 127;
            Bs[kk][cc] = Wd[(kc + kk) * V_ + cc];
        }
        __syncthreads();

#pragma unroll
        for (int k = 0; k < 32; k++) {
            float a[8], bb[8];
#pragma unroll
            for (int i = 0; i < 8; i++) a[i]  = As[k][ty + i * 16];
#pragma unroll
            for (int j = 0; j < 8; j++) bb[j] = Bs[k][tx + j * 16];
#pragma unroll
            for (int i = 0; i < 8; i++)
#pragma unroll
                for (int j = 0; j < 8; j++) acc[i][j] += a[i] * bb[j];
        }
    }

#pragma unroll
    for (int i = 0; i < 8; i++) {
        int r = r0 + ty + i * 16;
        int t = r >> 8;
        int b = r & 255;
#pragma unroll
        for (int j = 0; j < 8; j++) {
            int v = tx + j * 16;
            out[(size_t)b * T_ * V_ + (size_t)t * V_ + v] = acc[i][j] + bd[v];
        }
    }
}

// ---------------------------------------------------------------------------
extern "C" void kernel_launch(void* const* d_in, const int* in_sizes, int n_in,
                              void* d_out, int out_size) {
    const int*   X    = (const int*)  d_in[0];
    const float* h0   = (const float*)d_in[1];
    const float* c0   = (const float*)d_in[2];
    const float* emb  = (const float*)d_in[3];
    const float* Wx   = (const float*)d_in[4];
    const float* Wh   = (const float*)d_in[5];
    const float* bias = (const float*)d_in[6];
    const float* Wd   = (const float*)d_in[7];
    const float* bd   = (const float*)d_in[8];
    float* out = (float*)d_out;

    cudaFuncSetAttribute(lstm_persistent, cudaFuncAttributeMaxDynamicSharedMemorySize, SMEM_TOTAL_LSTM);

    init_kernel<<<(B_ * N_ + 255) / 256, 256>>>(h0);
    input_gemm<<<dim3(G4 / 128, (T_ * B_) / 128), 256>>>(X, emb, Wx, bias);
    lstm_persistent<<<NBLK, 256, SMEM_TOTAL_LSTM>>>(Wh, c0);
    out_gemm<<<(T_ * B_) / 128, 256>>>(Wd, bd, out);
}

// round 6
// speedup vs baseline: 2.8926x; 1.1466x over previous
#include <cuda_runtime.h>
#include <cuda_bf16.h>
#include <math.h>

#define B_  256
#define T_  256
#define E_  64
#define N_  512
#define V_  128
#define G4  2048   // 4*N
#define NBLK 128

#define KS_BF 520   // Whs row stride in bf16 (col-major-by-col: [col][k]), padded
#define KS_W  260   // same in 32-bit words
#define HA_BF 72    // hA row stride in bf16 ([row][k] per 64-k chunk), padded
#define HA_W  36    // same in 32-bit words
#define Z_STRIDE 68 // z-exchange float stride

// SMEM byte offsets (recurrence)
#define OFF_WHI 0
#define OFF_WLO (64 * KS_BF * 2)                 // 66560
#define OFF_HA  (2 * 64 * KS_BF * 2)             // 133120
#define HA_BYTES (64 * HA_BF * 2)                // 9216
#define SMEM_TOTAL_LSTM (OFF_HA + 4 * HA_BYTES)  // 169984

// GEMM kernels (input/out): 4 planes of [128][36 words]
#define GW 36
#define PLANE (128 * GW)                          // words per plane
#define SMEM_GEMM (4 * PLANE * 4)                 // 73728 bytes

// ---- scratch (static device memory; no allocations) ----
__device__ float g_xz[(size_t)T_ * B_ * G4];   // [T,B,4N] input projections (+bias)
__device__ float g_hs[(size_t)T_ * B_ * N_];   // [T,B,N] hidden states for final dense
__device__ float g_h[2][B_ * N_];              // ping-pong h
__device__ unsigned g_flags[NBLK * 32];        // grid barrier flags, 128B-padded

// ---------------------------------------------------------------------------
__device__ __forceinline__ float sigf(float x) { return 1.f / (1.f + __expf(-x)); }

__device__ __forceinline__ void mma_bf16(float* d, const unsigned* a, const unsigned* b) {
    asm volatile(
        "mma.sync.aligned.m16n8k16.row.col.f32.bf16.bf16.f32 "
        "{%0,%1,%2,%3}, {%4,%5,%6,%7}, {%8,%9}, {%0,%1,%2,%3};"
        : "+f"(d[0]), "+f"(d[1]), "+f"(d[2]), "+f"(d[3])
        : "r"(a[0]), "r"(a[1]), "r"(a[2]), "r"(a[3]), "r"(b[0]), "r"(b[1]));
}

__device__ __forceinline__ void bf16_split(float x, __nv_bfloat16& hi, __nv_bfloat16& lo) {
    hi = __float2bfloat16(x);
    lo = __float2bfloat16(x - __bfloat162float(hi));
}

// pack two bf16 into a 32-bit word: lo half in bits[0:16), hi half in bits[16:32)
__device__ __forceinline__ unsigned pack_bf2(__nv_bfloat16 lo, __nv_bfloat16 hi) {
    unsigned short ul = __bfloat16_as_ushort(lo);
    unsigned short uh = __bfloat16_as_ushort(hi);
    return (unsigned)ul | ((unsigned)uh << 16);
}

// split a float4 (4 consecutive k) into 2 hi-words and 2 lo-words
__device__ __forceinline__ void split4(float4 v, uint2& hw, uint2& lw) {
    __nv_bfloat16 h0, l0, h1, l1, h2, l2, h3, l3;
    bf16_split(v.x, h0, l0); bf16_split(v.y, h1, l1);
    bf16_split(v.z, h2, l2); bf16_split(v.w, h3, l3);
    hw = make_uint2(pack_bf2(h0, h1), pack_bf2(h2, h3));
    lw = make_uint2(pack_bf2(l0, l1), pack_bf2(l2, l3));
}

extern __shared__ char smem_raw[];

// ---------------------------------------------------------------------------
// init: load h_0, reset barrier flags (part of the graph -> replay-safe)
// ---------------------------------------------------------------------------
__global__ void init_kernel(const float* __restrict__ h0) {
    int i = blockIdx.x * blockDim.x + threadIdx.x;
    if (i < B_ * N_) g_h[0][i] = h0[i];
    if (i < NBLK)    g_flags[i * 32] = 0u;
}

// ---------------------------------------------------------------------------
// bf16x2 tensor-core GEMM core: block tile 128 rows x 128 cols, warp 32x64.
// SMEM planes (words): Ahi, Alo [row][k 0..63 as 32 words, stride GW],
//                      Bhi, Blo [col][k ...].
// Runs one 64-k chunk already staged; accumulates into acc[2][8][4].
// ---------------------------------------------------------------------------
__device__ __forceinline__ void gemm_chunk(const unsigned* AhiW, const unsigned* AloW,
                                           const unsigned* BhiW, const unsigned* BloW,
                                           int wr, int wc, int g4r, int lk,
                                           float acc[2][8][4]) {
#pragma unroll
    for (int k16 = 0; k16 < 4; k16++) {
        unsigned aHi[2][4], aLo[2][4];
#pragma unroll
        for (int f = 0; f < 2; f++) {
            int aw = (wr + f * 16 + g4r) * GW + lk + k16 * 8;
            aHi[f][0] = AhiW[aw];          aHi[f][1] = AhiW[aw + 8 * GW];
            aHi[f][2] = AhiW[aw + 4];      aHi[f][3] = AhiW[aw + 8 * GW + 4];
            aLo[f][0] = AloW[aw];          aLo[f][1] = AloW[aw + 8 * GW];
            aLo[f][2] = AloW[aw + 4];      aLo[f][3] = AloW[aw + 8 * GW + 4];
        }
#pragma unroll
        for (int sub = 0; sub < 8; sub++) {
            int col = wc + sub * 8 + g4r;
            int bw  = col * GW + lk + k16 * 8;
            unsigned bHi[2], bLo[2];
            bHi[0] = BhiW[bw]; bHi[1] = BhiW[bw + 4];
            bLo[0] = BloW[bw]; bLo[1] = BloW[bw + 4];
#pragma unroll
            for (int f = 0; f < 2; f++) {
                mma_bf16(acc[f][sub], aHi[f], bHi);
                mma_bf16(acc[f][sub], aHi[f], bLo);
                mma_bf16(acc[f][sub], aLo[f], bHi);
            }
        }
    }
}

// ---------------------------------------------------------------------------
// Kernel A (tensor): xz[r][g] = bias[g] + sum_e emb[X[b][t]][e] * Wx[e][g]
//   grid (16, 512): 128 cols x 128 rows per block. K = 64 (single chunk).
// ---------------------------------------------------------------------------
__global__ void __launch_bounds__(256)
input_gemm_tc(const int*   __restrict__ X,
              const float* __restrict__ emb,
              const float* __restrict__ Wx,
              const float* __restrict__ bias) {
    unsigned* AhiW = (unsigned*)smem_raw;
    unsigned* AloW = AhiW + PLANE;
    unsigned* BhiW = AloW + PLANE;
    unsigned* BloW = BhiW + PLANE;
    __shared__ int xid[128];

    const int tid  = threadIdx.x;
    const int r0   = blockIdx.y * 128;
    const int g0   = blockIdx.x * 128;
    const int lane = tid & 31;
    const int wid  = tid >> 5;
    const int wr   = (wid & 3) * 32;
    const int wc   = (wid >> 2) * 64;
    const int g4r  = lane >> 2;
    const int lk   = lane & 3;
    const int lx2  = lk * 2;

    if (tid < 128) {
        int r = r0 + tid;
        xid[tid] = X[(r & 255) * T_ + (r >> 8)];
    }
    __syncthreads();

    // stage A: emb rows gathered, split. row = tid>>1, quads (tid&1)*8+q
    {
        int row = tid >> 1;
        const float* src = emb + (size_t)xid[row] * E_;
        int qb = (tid & 1) * 8;
#pragma unroll
        for (int q = 0; q < 8; q++) {
            float4 v = *(const float4*)(src + (qb + q) * 4);
            uint2 hw, lw;
            split4(v, hw, lw);
            int widx = row * GW + (qb + q) * 2;
            *(uint2*)(AhiW + widx) = hw;
            *(uint2*)(AloW + widx) = lw;
        }
    }
    // stage B: Wx[k][g0+c] -> Bs[col][k]
    {
        int c = tid & 127, khalf = tid >> 7;
#pragma unroll
        for (int kk = 0; kk < 16; kk++) {
            int k0 = khalf * 32 + kk * 2;
            float a = Wx[(size_t)k0 * G4 + g0 + c];
            float b = Wx[(size_t)(k0 + 1) * G4 + g0 + c];
            __nv_bfloat16 ha, la, hb, lb;
            bf16_split(a, ha, la); bf16_split(b, hb, lb);
            int widx = c * GW + khalf * 16 + kk;
            BhiW[widx] = pack_bf2(ha, hb);
            BloW[widx] = pack_bf2(la, lb);
        }
    }
    __syncthreads();

    float acc[2][8][4];
#pragma unroll
    for (int f = 0; f < 2; f++)
#pragma unroll
        for (int s = 0; s < 8; s++)
#pragma unroll
            for (int i = 0; i < 4; i++) acc[f][s][i] = 0.f;

    gemm_chunk(AhiW, AloW, BhiW, BloW, wr, wc, g4r, lk, acc);

    // epilogue: xz[r][g] = acc + bias[g]
#pragma unroll
    for (int f = 0; f < 2; f++) {
        int rlo = r0 + wr + f * 16 + g4r;
#pragma unroll
        for (int sub = 0; sub < 8; sub++) {
            int g = g0 + wc + sub * 8 + lx2;
            float2 bb = *(const float2*)(bias + g);
            *(float2*)(g_xz + (size_t)rlo * G4 + g) =
                make_float2(acc[f][sub][0] + bb.x, acc[f][sub][1] + bb.y);
            *(float2*)(g_xz + (size_t)(rlo + 8) * G4 + g) =
                make_float2(acc[f][sub][2] + bb.x, acc[f][sub][3] + bb.y);
        }
    }
}

// ---------------------------------------------------------------------------
// Persistent LSTM recurrence, bf16x2 error-compensated tensor-core GEMM.
//   (unchanged from R5)
// ---------------------------------------------------------------------------
__global__ void __launch_bounds__(256, 1)
lstm_persistent(const float* __restrict__ Wh, const float* __restrict__ c0) {
    __nv_bfloat16* WhHi = (__nv_bfloat16*)(smem_raw + OFF_WHI);
    __nv_bfloat16* WhLo = (__nv_bfloat16*)(smem_raw + OFF_WLO);
    const unsigned* WhHiW = (const unsigned*)WhHi;
    const unsigned* WhLoW = (const unsigned*)WhLo;

    char* hBase = smem_raw + OFF_HA;   // 4 buffers: hi0, lo0, hi1, lo1

    const int tid  = threadIdx.x;
    const int bid  = blockIdx.x;
    const int cg   = bid & 31;          // n-group
    const int rg   = bid >> 5;          // row-group
    const int n0   = cg * 16;
    const int r0   = rg * 64;
    const int lane = tid & 31;
    const int wid  = tid >> 5;
    const int wr   = (wid & 3) * 16;    // warp row offset in tile
    const int wc   = (wid >> 2) * 32;   // warp col offset in tile
    const int g4r  = lane >> 2;         // 0..7
    const int lk   = lane & 3;          // 0..3
    const int lx2  = lk * 2;

    // ---- load + split Wh slice once: WhHi/WhLo[col][k], col = g*16+j ----
    for (int idx = tid; idx < 512 * 16; idx += 256) {
        int k = idx >> 4, q = idx & 15;
        int g = q >> 2, jj = (q & 3) * 4;
        float4 w = *(const float4*)(Wh + (size_t)k * G4 + g * N_ + n0 + jj);
        int cb = g * 16 + jj;
        __nv_bfloat16 hi, lo;
        bf16_split(w.x, hi, lo); WhHi[(cb + 0) * KS_BF + k] = hi; WhLo[(cb + 0) * KS_BF + k] = lo;
        bf16_split(w.y, hi, lo); WhHi[(cb + 1) * KS_BF + k] = hi; WhLo[(cb + 1) * KS_BF + k] = lo;
        bf16_split(w.z, hi, lo); WhHi[(cb + 2) * KS_BF + k] = hi; WhLo[(cb + 2) * KS_BF + k] = lo;
        bf16_split(w.w, hi, lo); WhHi[(cb + 3) * KS_BF + k] = hi; WhLo[(cb + 3) * KS_BF + k] = lo;
    }

    // ---- cell state in registers for the whole run ----
    const int prow = tid >> 2;             // 0..63
    const int pj0  = (tid & 3) * 4;        // 0,4,8,12
    float4 creg = *(const float4*)(c0 + (size_t)(r0 + prow) * N_ + n0 + pj0);

    __syncthreads();

    const int srow0 = tid >> 4;            // rows tid>>4, +16, +32, +48
    const int skq   = tid & 15;            // k quad

    for (int t = 0; t < T_; t++) {
        const float* __restrict__ h_in  = g_h[t & 1];
        float*       __restrict__ h_out = g_h[(t + 1) & 1];

        // ---- acc init from xz ----
        float acc[4][4];
        {
            const int rlo = r0 + wr + g4r;
#pragma unroll
            for (int sub = 0; sub < 4; sub++) {
                int c    = wc + sub * 8 + lx2;
                int gate = c >> 4, jj = c & 15;
                size_t base = (size_t)t * B_ * G4 + (size_t)gate * N_ + n0 + jj;
                float2 xlo = __ldcg((const float2*)(g_xz + base + (size_t)rlo * G4));
                float2 xhi = __ldcg((const float2*)(g_xz + base + (size_t)(rlo + 8) * G4));
                acc[sub][0] = xlo.x; acc[sub][1] = xlo.y;
                acc[sub][2] = xhi.x; acc[sub][3] = xhi.y;
            }
        }

        float4 pf[4];
#pragma unroll
        for (int q = 0; q < 4; q++) {
            pf[q] = __ldcg((const float4*)(h_in + (size_t)(r0 + srow0 + q * 16) * N_ + skq * 4));
        }

        for (int kc = 0; kc < 8; kc++) {
            unsigned* hHiW = (unsigned*)(hBase + (kc & 1) * 2 * HA_BYTES);
            unsigned* hLoW = hHiW + HA_BYTES / 4;

#pragma unroll
            for (int q = 0; q < 4; q++) {
                int row = srow0 + q * 16;
                uint2 hw, lw;
                split4(pf[q], hw, lw);
                int widx = row * HA_W + skq * 2;
                *(uint2*)(hHiW + widx) = hw;
                *(uint2*)(hLoW + widx) = lw;
            }
            if (kc < 7) {
#pragma unroll
                for (int q = 0; q < 4; q++) {
                    pf[q] = __ldcg((const float4*)(h_in + (size_t)(r0 + srow0 + q * 16) * N_ + (kc + 1) * 64 + skq * 4));
                }
            }
            __syncthreads();

            const int aBase = (wr + g4r) * HA_W + lk;
#pragma unroll
            for (int k16 = 0; k16 < 4; k16++) {
                const int aw = aBase + k16 * 8;
                unsigned aHi[4], aLo[4];
                aHi[0] = hHiW[aw];              aHi[1] = hHiW[aw + 8 * HA_W];
                aHi[2] = hHiW[aw + 4];          aHi[3] = hHiW[aw + 8 * HA_W + 4];
                aLo[0] = hLoW[aw];              aLo[1] = hLoW[aw + 8 * HA_W];
                aLo[2] = hLoW[aw + 4];          aLo[3] = hLoW[aw + 8 * HA_W + 4];
                const int kAbs = kc * 32 + lk + k16 * 8;
#pragma unroll
                for (int sub = 0; sub < 4; sub++) {
                    const int col = wc + sub * 8 + g4r;
                    const int bw  = col * KS_W + kAbs;
                    unsigned bHi[2], bLo[2];
                    bHi[0] = WhHiW[bw]; bHi[1] = WhHiW[bw + 4];
                    bLo[0] = WhLoW[bw]; bLo[1] = WhLoW[bw + 4];
                    mma_bf16(acc[sub], aHi, bHi);
                    mma_bf16(acc[sub], aHi, bLo);
                    mma_bf16(acc[sub], aLo, bHi);
                }
            }
            __syncthreads();
        }

        // ---- exchange z through SMEM ----
        float* zs = (float*)hBase;
        {
            const int rl = wr + g4r;
#pragma unroll
            for (int sub = 0; sub < 4; sub++) {
                int c = wc + sub * 8 + lx2;
                *(float2*)(zs + (size_t)rl * Z_STRIDE + c)       = make_float2(acc[sub][0], acc[sub][1]);
                *(float2*)(zs + (size_t)(rl + 8) * Z_STRIDE + c) = make_float2(acc[sub][2], acc[sub][3]);
            }
        }
        __syncthreads();

        // ---- pointwise gates + c/h update ----
        {
            const float* zr = zs + (size_t)prow * Z_STRIDE + pj0;
            float4 zi = *(const float4*)(zr + 0);
            float4 zf = *(const float4*)(zr + 16);
            float4 zg = *(const float4*)(zr + 32);
            float4 zo = *(const float4*)(zr + 48);

            float4 hv;
            creg.x = sigf(zf.x) * creg.x + sigf(zi.x) * tanhf(zg.x); hv.x = sigf(zo.x) * tanhf(creg.x);
            creg.y = sigf(zf.y) * creg.y + sigf(zi.y) * tanhf(zg.y); hv.y = sigf(zo.y) * tanhf(creg.y);
            creg.z = sigf(zf.z) * creg.z + sigf(zi.z) * tanhf(zg.z); hv.z = sigf(zo.z) * tanhf(creg.z);
            creg.w = sigf(zf.w) * creg.w + sigf(zi.w) * tanhf(zg.w); hv.w = sigf(zo.w) * tanhf(creg.w);

            size_t off = (size_t)(r0 + prow) * N_ + n0 + pj0;
            *(float4*)(h_out + off) = hv;
            *(float4*)(g_hs + (size_t)t * B_ * N_ + off) = hv;
        }

        // ---- grid barrier ----
        __threadfence();
        __syncthreads();
        if (tid == 0) {
            asm volatile("st.global.release.gpu.u32 [%0], %1;"
                         :: "l"(&g_flags[bid * 32]), "r"((unsigned)(t + 1)) : "memory");
        }
        if (tid < NBLK) {
            unsigned v;
            do {
                asm volatile("ld.global.acquire.gpu.u32 %0, [%1];"
                             : "=r"(v) : "l"(&g_flags[tid * 32]) : "memory");
                if (v >= (unsigned)(t + 1)) break;
                __nanosleep(20);
            } while (true);
        }
        __syncthreads();
    }
}

// ---------------------------------------------------------------------------
// Kernel D (tensor): logits[b][t][v] = bd[v] + sum_n hs[t][b][n] * Wd[n][v]
//   grid 512: 128 rows x 128 cols (all of V) per block; K=512 in 8 chunks.
// ---------------------------------------------------------------------------
__global__ void __launch_bounds__(256)
out_gemm_tc(const float* __restrict__ Wd,
            const float* __restrict__ bd,
            float*       __restrict__ out) {
    unsigned* AhiW = (unsigned*)smem_raw;
    unsigned* AloW = AhiW + PLANE;
    unsigned* BhiW = AloW + PLANE;
    unsigned* BloW = BhiW + PLANE;

    const int tid  = threadIdx.x;
    const int r0   = blockIdx.x * 128;
    const int lane = tid & 31;
    const int wid  = tid >> 5;
    const int wr   = (wid & 3) * 32;
    const int wc   = (wid >> 2) * 64;
    const int g4r  = lane >> 2;
    const int lk   = lane & 3;
    const int lx2  = lk * 2;

    float acc[2][8][4];
#pragma unroll
    for (int f = 0; f < 2; f++)
#pragma unroll
        for (int s = 0; s < 8; s++)
#pragma unroll
            for (int i = 0; i < 4; i++) acc[f][s][i] = 0.f;

    const int srow = tid >> 1;
    const int sqb  = (tid & 1) * 8;
    const int bc   = tid & 127;
    const int bkh  = tid >> 7;

    for (int kc = 0; kc < 8; kc++) {
        // stage A: g_hs rows, split
#pragma unroll
        for (int q = 0; q < 8; q++) {
            float4 v = __ldcg((const float4*)(g_hs + (size_t)(r0 + srow) * N_ + kc * 64 + (sqb + q) * 4));
            uint2 hw, lw;
            split4(v, hw, lw);
            int widx = srow * GW + (sqb + q) * 2;
            *(uint2*)(AhiW + widx) = hw;
            *(uint2*)(AloW + widx) = lw;
        }
        // stage B: Wd[k][v] -> Bs[col][k]
#pragma unroll
        for (int kk = 0; kk < 16; kk++) {
            int k0 = kc * 64 + bkh * 32 + kk * 2;
            float a = Wd[(size_t)k0 * V_ + bc];
            float b = Wd[(size_t)(k0 + 1) * V_ + bc];
            __nv_bfloat16 ha, la, hb, lb;
            bf16_split(a, ha, la); bf16_split(b, hb, lb);
            int widx = bc * GW + bkh * 16 + kk;
            BhiW[widx] = pack_bf2(ha, hb);
            BloW[widx] = pack_bf2(la, lb);
        }
        __syncthreads();

        gemm_chunk(AhiW, AloW, BhiW, BloW, wr, wc, g4r, lk, acc);
        __syncthreads();
    }

    // epilogue: out[b][t][v], r = t*256 + b
#pragma unroll
    for (int f = 0; f < 2; f++) {
        int rlo = r0 + wr + f * 16 + g4r;
        int t0 = rlo >> 8,        b0 = rlo & 255;
        int t1 = (rlo + 8) >> 8,  b1 = (rlo + 8) & 255;
        size_t o0 = ((size_t)b0 * T_ + t0) * V_;
        size_t o1 = ((size_t)b1 * T_ + t1) * V_;
#pragma unroll
        for (int sub = 0; sub < 8; sub++) {
            int v = wc + sub * 8 + lx2;
            float2 bb = *(const float2*)(bd + v);
            *(float2*)(out + o0 + v) = make_float2(acc[f][sub][0] + bb.x, acc[f][sub][1] + bb.y);
            *(float2*)(out + o1 + v) = make_float2(acc[f][sub][2] + bb.x, acc[f][sub][3] + bb.y);
        }
    }
}

// ---------------------------------------------------------------------------
extern "C" void kernel_launch(void* const* d_in, const int* in_sizes, int n_in,
                              void* d_out, int out_size) {
    const int*   X    = (const int*)  d_in[0];
    const float* h0   = (const float*)d_in[1];
    const float* c0   = (const float*)d_in[2];
    const float* emb  = (const float*)d_in[3];
    const float* Wx   = (const float*)d_in[4];
    const float* Wh   = (const float*)d_in[5];
    const float* bias = (const float*)d_in[6];
    const float* Wd   = (const float*)d_in[7];
    const float* bd   = (const float*)d_in[8];
    float* out = (float*)d_out;

    cudaFuncSetAttribute(lstm_persistent, cudaFuncAttributeMaxDynamicSharedMemorySize, SMEM_TOTAL_LSTM);
    cudaFuncSetAttribute(input_gemm_tc,  cudaFuncAttributeMaxDynamicSharedMemorySize, SMEM_GEMM);
    cudaFuncSetAttribute(out_gemm_tc,    cudaFuncAttributeMaxDynamicSharedMemorySize, SMEM_GEMM);

    init_kernel<<<(B_ * N_ + 255) / 256, 256>>>(h0);
    input_gemm_tc<<<dim3(G4 / 128, (T_ * B_) / 128), 256, SMEM_GEMM>>>(X, emb, Wx, bias);
    lstm_persistent<<<NBLK, 256, SMEM_TOTAL_LSTM>>>(Wh, c0);
    out_gemm_tc<<<(T_ * B_) / 128, 256, SMEM_GEMM>>>(Wd, bd, out);
}